// round 1
// baseline (speedup 1.0000x reference)
#include <cuda_runtime.h>

// I5Pool: out[b,c,h,w] = max_{j<=w} x[b,c,h,j] * guide[b,0,h,j]
// Shapes: x [8,256,128,128] fp32, guide [8,1,128,128] fp32.
// One warp per row of W=128; float4 loads; warp shuffle max-scan.

#define B_ 8
#define C_ 256
#define H_ 128
#define W_ 128
#define ROWS (B_ * C_ * H_)   // 262144

__global__ void __launch_bounds__(256) I5Pool_kernel(
    const float* __restrict__ x,
    const float* __restrict__ guide,
    float* __restrict__ out)
{
    const int warp_global = (blockIdx.x * blockDim.x + threadIdx.x) >> 5;
    const int lane = threadIdx.x & 31;
    if (warp_global >= ROWS) return;

    // row decomposition: warp_global = b*(C_*H_) + c*H_ + h
    const int h = warp_global & (H_ - 1);
    const int b = warp_global / (C_ * H_);

    const float4* xr = reinterpret_cast<const float4*>(x + (size_t)warp_global * W_);
    const float4* gr = reinterpret_cast<const float4*>(guide + ((size_t)b * H_ + h) * W_);

    const float4 xv = xr[lane];
    const float4 gv = gr[lane];

    // local serial prefix-max of 4 gated values
    const float v0 = xv.x * gv.x;
    const float v1 = fmaxf(v0, xv.y * gv.y);
    const float v2 = fmaxf(v1, xv.z * gv.z);
    const float v3 = fmaxf(v2, xv.w * gv.w);

    // warp inclusive max-scan on lane totals (v3)
    float m = v3;
    #pragma unroll
    for (int d = 1; d < 32; d <<= 1) {
        const float o = __shfl_up_sync(0xffffffffu, m, d);
        if (lane >= d) m = fmaxf(m, o);
    }
    // exclusive prefix for this lane
    float pre = __shfl_up_sync(0xffffffffu, m, 1);
    if (lane == 0) pre = __int_as_float(0xff800000); // -inf

    float4 ov;
    ov.x = fmaxf(v0, pre);
    ov.y = fmaxf(v1, pre);
    ov.z = fmaxf(v2, pre);
    ov.w = fmaxf(v3, pre);

    reinterpret_cast<float4*>(out + (size_t)warp_global * W_)[lane] = ov;
}

extern "C" void kernel_launch(void* const* d_in, const int* in_sizes, int n_in,
                              void* d_out, int out_size)
{
    const float* x     = (const float*)d_in[0];
    const float* guide = (const float*)d_in[1];
    float* out         = (float*)d_out;

    // 262144 warps, 8 warps (256 threads) per block -> 32768 blocks
    const int threads = 256;
    const int blocks  = (ROWS * 32) / threads;
    I5Pool_kernel<<<blocks, threads>>>(x, guide, out);
}

// round 3
// speedup vs baseline: 1.0463x; 1.0463x over previous
#include <cuda_runtime.h>

// I5Pool: out[b,c,h,w] = max_{j<=w} x[b,c,h,j] * guide[b,0,h,j]
// x [8,256,128,128] fp32, guide [8,1,128,128] fp32.
// 2 channel-rows per warp (shared guide row); float4; warp shuffle max-scan.
// x via __ldcs / out via __stcs (streaming, evict-first) so guide stays L2-hot.

#define B_ 8
#define C_ 256
#define H_ 128
#define W_ 128
#define ROWS    (B_ * C_ * H_)        // 262144
#define ROWPAIR (ROWS / 2)            // 131072 warps

__global__ void __launch_bounds__(256) I5Pool_kernel(
    const float* __restrict__ x,
    const float* __restrict__ guide,
    float* __restrict__ out)
{
    const int wg   = (blockIdx.x * blockDim.x + threadIdx.x) >> 5;
    const int lane = threadIdx.x & 31;
    if (wg >= ROWPAIR) return;

    // wg = b*(C_/2 * H_) + cp*H_ + h ; rows are c = 2*cp, 2*cp+1
    const int h  = wg & (H_ - 1);
    const int t  = wg >> 7;                 // b*(C_/2) + cp
    const int b  = t / (C_ / 2);
    const int cp = t - b * (C_ / 2);

    const size_t row0 = (((size_t)b * C_ + 2 * cp) * H_ + h) * W_;
    const size_t row1 = row0 + (size_t)H_ * W_;   // next channel, same (b,h)
    const size_t grow = ((size_t)b * H_ + h) * W_;

    // Front-batch all loads: guide (caching path) + 2 x rows (streaming path)
    const float4 gv = reinterpret_cast<const float4*>(guide + grow)[lane];
    const float4 xa = __ldcs(reinterpret_cast<const float4*>(x + row0) + lane);
    const float4 xb = __ldcs(reinterpret_cast<const float4*>(x + row1) + lane);

    // local serial prefix-max (4 elems), two independent rows
    const float a0 = xa.x * gv.x;
    const float a1 = fmaxf(a0, xa.y * gv.y);
    const float a2 = fmaxf(a1, xa.z * gv.z);
    const float a3 = fmaxf(a2, xa.w * gv.w);

    const float b0 = xb.x * gv.x;
    const float b1 = fmaxf(b0, xb.y * gv.y);
    const float b2 = fmaxf(b1, xb.z * gv.z);
    const float b3 = fmaxf(b2, xb.w * gv.w);

    // interleaved warp inclusive max-scans (ILP across the two rows)
    float ma = a3, mb = b3;
    #pragma unroll
    for (int d = 1; d < 32; d <<= 1) {
        const float oa = __shfl_up_sync(0xffffffffu, ma, d);
        const float ob = __shfl_up_sync(0xffffffffu, mb, d);
        if (lane >= d) { ma = fmaxf(ma, oa); mb = fmaxf(mb, ob); }
    }
    float pa = __shfl_up_sync(0xffffffffu, ma, 1);
    float pb = __shfl_up_sync(0xffffffffu, mb, 1);
    if (lane == 0) {
        pa = __int_as_float(0xff800000);  // -inf
        pb = __int_as_float(0xff800000);
    }

    float4 oa4, ob4;
    oa4.x = fmaxf(a0, pa); oa4.y = fmaxf(a1, pa);
    oa4.z = fmaxf(a2, pa); oa4.w = fmaxf(a3, pa);
    ob4.x = fmaxf(b0, pb); ob4.y = fmaxf(b1, pb);
    ob4.z = fmaxf(b2, pb); ob4.w = fmaxf(b3, pb);

    __stcs(reinterpret_cast<float4*>(out + row0) + lane, oa4);
    __stcs(reinterpret_cast<float4*>(out + row1) + lane, ob4);
}

extern "C" void kernel_launch(void* const* d_in, const int* in_sizes, int n_in,
                              void* d_out, int out_size)
{
    const float* x     = (const float*)d_in[0];
    const float* guide = (const float*)d_in[1];
    float* out         = (float*)d_out;

    const int threads = 256;                       // 8 warps/block
    const int blocks  = (ROWPAIR * 32) / threads;  // 16384 blocks
    I5Pool_kernel<<<blocks, threads>>>(x, guide, out);
}